// round 9
// baseline (speedup 1.0000x reference)
#include <cuda_runtime.h>
#include <cuda_bf16.h>
#include <math.h>
#include <stdint.h>

// Problem constants
#define BATCH   4
#define SEQ     8192
#define MROWS   (BATCH * SEQ)   // 32768
#define DIM     256
#define NCLS    1000
#define EPS_F   1e-5f

#define BK  32
#define LDT 40                  // 80B padded row: 16B-aligned, ldmatrix-clean

// Proj: CTA 64x256, 8 warps (2M x 4N), warp 32x64, 3-stage cp.async
#define PM 64
#define PN 256
#define P_A_STG (PM * LDT * 2)             // 5120 B
#define P_B_STG (PN * LDT * 2)             // 20480 B
#define PROJ_SMEM (3 * (P_A_STG + P_B_STG))  // 76800 B

// Logits: CTA 128x128, 8 warps (4M x 2N), warp 32x64.
// B (P-tile) resident full-K; A 2-stage; each CTA streams MT m-tiles.
#define BM 128
#define BN 128
#define MT 8
#define CHUNK (BM * LDT * 2)               // 10240 B
#define LG_SMEM (8 * CHUNK + 2 * CHUNK)    // 102400 B

// Scratch
__device__ __nv_bfloat16 g_featb[MROWS * DIM];
__device__ __nv_bfloat16 g_Wb[DIM * DIM];
__device__ __nv_bfloat16 g_xb[MROWS * DIM];
__device__ float         g_xsq[MROWS];
__device__ __nv_bfloat16 g_pb[NCLS * DIM];
__device__ float         g_psq[NCLS];

// ---------------------------------------------------------------------------
// PTX helpers (base-sm_103-legal only)
// ---------------------------------------------------------------------------
__device__ __forceinline__ uint32_t smem_u32(const void* p) {
    return (uint32_t)__cvta_generic_to_shared(p);
}
__device__ __forceinline__ void cp16s(uint32_t dst_saddr, const void* src, bool valid)
{
    int sz = valid ? 16 : 0;
    asm volatile("cp.async.cg.shared.global [%0], [%1], 16, %2;\n"
                 :: "r"(dst_saddr), "l"(src), "r"(sz));
}
#define CP_COMMIT() asm volatile("cp.async.commit_group;\n" ::: "memory")
#define CP_WAIT(n)  asm volatile("cp.async.wait_group %0;\n" :: "n"(n) : "memory")

__device__ __forceinline__ void ldm_x4(uint32_t& r0, uint32_t& r1,
                                       uint32_t& r2, uint32_t& r3, uint32_t saddr)
{
    asm volatile("ldmatrix.sync.aligned.m8n8.x4.shared.b16 {%0,%1,%2,%3}, [%4];"
                 : "=r"(r0), "=r"(r1), "=r"(r2), "=r"(r3) : "r"(saddr));
}

__device__ __forceinline__ void mma16816(float acc[4], uint32_t a0, uint32_t a1,
                                         uint32_t a2, uint32_t a3,
                                         uint32_t b0, uint32_t b1)
{
    asm volatile(
        "mma.sync.aligned.m16n8k16.row.col.f32.bf16.bf16.f32 "
        "{%0,%1,%2,%3}, {%4,%5,%6,%7}, {%8,%9}, {%0,%1,%2,%3};\n"
        : "+f"(acc[0]), "+f"(acc[1]), "+f"(acc[2]), "+f"(acc[3])
        : "r"(a0), "r"(a1), "r"(a2), "r"(a3), "r"(b0), "r"(b1));
}

// ---------------------------------------------------------------------------
// fp32 -> bf16 convert
// ---------------------------------------------------------------------------
__global__ void f2b_kernel(const float* __restrict__ in,
                           __nv_bfloat16* __restrict__ out, int n)
{
    int i = (blockIdx.x * blockDim.x + threadIdx.x) * 4;
    if (i < n) {
        float4 v = *(const float4*)(in + i);
        __nv_bfloat162 lo = __floats2bfloat162_rn(v.x, v.y);
        __nv_bfloat162 hi = __floats2bfloat162_rn(v.z, v.w);
        uint2 pk;
        pk.x = *(uint32_t*)&lo;
        pk.y = *(uint32_t*)&hi;
        *(uint2*)(out + i) = pk;
    }
}

// ---------------------------------------------------------------------------
// Proj: xb = expmap0(featb @ Wb^T + b), 3-stage cp.async, CTA 64x256
// ---------------------------------------------------------------------------
__global__ __launch_bounds__(256, 2)
void proj_expmap_kernel(const __nv_bfloat16* __restrict__ Ab,
                        const __nv_bfloat16* __restrict__ Wb,
                        const float* __restrict__ bias,
                        __nv_bfloat16* __restrict__ Xb,
                        float* __restrict__ xsq_out)
{
    extern __shared__ __nv_bfloat16 dsm[];
    const uint32_t base = smem_u32(dsm);
    __shared__ float rowsum[PM];
    __shared__ float rowscale[PM];

    const int tid = threadIdx.x;
    const int m0  = blockIdx.x * PM;
    if (tid < PM) rowsum[tid] = 0.f;

    const int warp = tid >> 5;
    const int lane = tid & 31;
    const int wm = (warp & 1) * 32;       // 2 warps in M
    const int wn = (warp >> 1) * 64;      // 4 warps in N
    const int g  = lane >> 2;
    const int tg = lane & 3;
    const int lrow16 = lane & 15;
    const int khalf  = (lane >> 4) << 3;

    const int lrow = tid >> 2;            // 0..63
    const int lch  = (tid & 3) * 8;

    float acc[2][8][4];
    #pragma unroll
    for (int i = 0; i < 2; i++)
        #pragma unroll
        for (int j = 0; j < 8; j++)
            #pragma unroll
            for (int e = 0; e < 4; e++) acc[i][j][e] = 0.f;

    auto load_stage = [&](int kt) {
        const int st = kt % 3;
        const int k0 = kt * BK;
        cp16s(base + st * P_A_STG + (uint32_t)(lrow * LDT + lch) * 2u,
              &Ab[(size_t)(m0 + lrow) * DIM + k0 + lch], true);
        #pragma unroll
        for (int r = 0; r < 4; r++) {
            int row = lrow + r * 64;
            cp16s(base + 3 * P_A_STG + st * P_B_STG + (uint32_t)(row * LDT + lch) * 2u,
                  &Wb[(size_t)row * DIM + k0 + lch], true);
        }
        CP_COMMIT();
    };

    load_stage(0);
    load_stage(1);

    const int NKT = DIM / BK;   // 8
    for (int kt = 0; kt < NKT; kt++) {
        if (kt < NKT - 1) CP_WAIT(1); else CP_WAIT(0);
        __syncthreads();
        if (kt + 2 < NKT) load_stage(kt + 2);

        const int st = kt % 3;
        const uint32_t ab = base + st * P_A_STG;
        const uint32_t bb = base + 3 * P_A_STG + st * P_B_STG;

        #pragma unroll
        for (int ks = 0; ks < 2; ks++) {
            const int kc = ks * 16 + khalf;
            uint32_t a[2][4];
            #pragma unroll
            for (int i = 0; i < 2; i++)
                ldm_x4(a[i][0], a[i][1], a[i][2], a[i][3],
                       ab + (uint32_t)((wm + i * 16 + lrow16) * LDT + kc) * 2u);
            #pragma unroll
            for (int jj = 0; jj < 4; jj++) {
                uint32_t b0, b1, b2, b3;
                ldm_x4(b0, b1, b2, b3,
                       bb + (uint32_t)((wn + jj * 16 + lrow16) * LDT + kc) * 2u);
                #pragma unroll
                for (int i = 0; i < 2; i++) {
                    mma16816(acc[i][2 * jj + 0], a[i][0], a[i][1], a[i][2], a[i][3], b0, b2);
                    mma16816(acc[i][2 * jj + 1], a[i][0], a[i][1], a[i][2], a[i][3], b1, b3);
                }
            }
        }
        __syncthreads();
    }

    // epilogue: bias, row sumsq, expmap, write
    float part[2][2] = {{0.f, 0.f}, {0.f, 0.f}};
    #pragma unroll
    for (int j = 0; j < 8; j++) {
        const int nb = wn + j * 8 + tg * 2;
        const float b0 = bias[nb], b1 = bias[nb + 1];
        #pragma unroll
        for (int i = 0; i < 2; i++) {
            #pragma unroll
            for (int h = 0; h < 2; h++) {
                float y0 = acc[i][j][2 * h + 0] + b0;
                float y1 = acc[i][j][2 * h + 1] + b1;
                acc[i][j][2 * h + 0] = y0;
                acc[i][j][2 * h + 1] = y1;
                part[i][h] += y0 * y0 + y1 * y1;
            }
        }
    }
    #pragma unroll
    for (int i = 0; i < 2; i++)
        #pragma unroll
        for (int h = 0; h < 2; h++)
            atomicAdd(&rowsum[wm + i * 16 + g + h * 8], part[i][h]);
    __syncthreads();

    if (tid < PM) {
        const float total = rowsum[tid];
        const float norm  = sqrtf(total);
        const float cn    = fmaxf(norm, EPS_F);
        const float s     = tanhf(cn) / cn;
        rowscale[tid] = s;
        xsq_out[m0 + tid] = s * s * total;
    }
    __syncthreads();

    #pragma unroll
    for (int i = 0; i < 2; i++) {
        #pragma unroll
        for (int h = 0; h < 2; h++) {
            const int ml = wm + i * 16 + g + h * 8;
            const float s = rowscale[ml];
            const int m = m0 + ml;
            #pragma unroll
            for (int j = 0; j < 8; j++) {
                const int nb = wn + j * 8 + tg * 2;
                __nv_bfloat162 v = __floats2bfloat162_rn(
                    s * acc[i][j][2 * h + 0], s * acc[i][j][2 * h + 1]);
                *(__nv_bfloat162*)&Xb[(size_t)m * DIM + nb] = v;
            }
        }
    }
}

// ---------------------------------------------------------------------------
// expmap0 for embeddings
// ---------------------------------------------------------------------------
__global__ void expmap_kernel(const float* __restrict__ src,
                              __nv_bfloat16* __restrict__ dst,
                              float* __restrict__ sq_out)
{
    const int row = blockIdx.x;
    const int tid = threadIdx.x;
    const float v = src[(size_t)row * DIM + tid];

    float s = v * v;
    #pragma unroll
    for (int off = 16; off > 0; off >>= 1)
        s += __shfl_xor_sync(0xFFFFFFFFu, s, off);

    __shared__ float warp_s[8];
    __shared__ float total_sh;
    const int warp = tid >> 5;
    if ((tid & 31) == 0) warp_s[warp] = s;
    __syncthreads();
    if (tid == 0) {
        float t = 0.f;
        #pragma unroll
        for (int w = 0; w < 8; w++) t += warp_s[w];
        total_sh = t;
    }
    __syncthreads();

    const float total = total_sh;
    const float norm  = sqrtf(total);
    const float cn    = fmaxf(norm, EPS_F);
    const float scale = tanhf(cn) / cn;

    dst[(size_t)row * DIM + tid] = __float2bfloat16(scale * v);
    if (tid == 0) sq_out[row] = scale * scale * total;
}

// ---------------------------------------------------------------------------
// Logits: persistent-B. Each CTA: one N-tile (B resident, full K) x MT m-tiles
// streamed through a 2-stage A pipeline. Poincare epilogue per m-tile.
// ---------------------------------------------------------------------------
__global__ __launch_bounds__(256, 2)
void logits_mma_kernel(const __nv_bfloat16* __restrict__ Xb,
                       const __nv_bfloat16* __restrict__ Pb,
                       const float* __restrict__ xsq,
                       const float* __restrict__ psq,
                       const float* __restrict__ logit_scale,
                       float* __restrict__ Out)
{
    extern __shared__ __nv_bfloat16 dsm[];
    const uint32_t bfull = smem_u32(dsm);          // 8 chunks of B
    const uint32_t astg  = bfull + 8 * CHUNK;      // 2 A stages

    const int tid  = threadIdx.x;
    const int n0    = blockIdx.x * BN;
    const int mbase = blockIdx.y * MT;             // first m-tile index

    const int warp = tid >> 5;
    const int lane = tid & 31;
    const int wm = (warp & 3) * 32;
    const int wn = (warp >> 2) * 64;
    const int g  = lane >> 2;
    const int tg = lane & 3;
    const int lrow16 = lane & 15;
    const int khalf  = (lane >> 4) << 3;

    const int lrow = tid >> 2;            // 0..63
    const int lch  = (tid & 3) * 8;

    // ---- load B (P-tile) full-K once: 4096 x 16B chunks (group 0)
    #pragma unroll
    for (int it = 0; it < 16; it++) {
        int idx = tid + it * 256;
        int row = idx >> 5;
        int colh = (idx & 31) * 8;
        int kc = colh >> 5;
        int cc = colh & 31;
        cp16s(bfull + (uint32_t)((kc * BM + row) * LDT + cc) * 2u,
              &Pb[(size_t)(n0 + row) * DIM + colh], (n0 + row) < NCLS);
    }
    CP_COMMIT();

    // A stage loader: q = mt*8 + kt, stage q&1
    auto loadA = [&](int q) {
        const int mt = q >> 3, kt = q & 7, st = q & 1;
        const int m0 = (mbase + mt) * BM;
        const int k0 = kt * BK;
        #pragma unroll
        for (int r = 0; r < 2; r++) {
            int row = lrow + r * 64;
            cp16s(astg + (uint32_t)((st * BM + row) * LDT + lch) * 2u,
                  &Xb[(size_t)(m0 + row) * DIM + k0 + lch], true);
        }
        CP_COMMIT();
    };

    loadA(0);
    loadA(1);

    const float lscale = fminf(expf(logit_scale[0]), 100.f);
    const int QMAX = MT * 8;   // 64

    for (int mt = 0; mt < MT; mt++) {
        const int m0 = (mbase + mt) * BM;

        float acc[2][8][4];
        #pragma unroll
        for (int i = 0; i < 2; i++)
            #pragma unroll
            for (int j = 0; j < 8; j++)
                #pragma unroll
                for (int e = 0; e < 4; e++) acc[i][j][e] = 0.f;

        for (int kt = 0; kt < 8; kt++) {
            const int q = mt * 8 + kt;
            if (q < QMAX - 1) CP_WAIT(1); else CP_WAIT(0);
            __syncthreads();

            const uint32_t ab = astg + (uint32_t)((q & 1) * BM * LDT) * 2u;
            const uint32_t bb = bfull + (uint32_t)(kt * BM * LDT) * 2u;

            #pragma unroll
            for (int ks = 0; ks < 2; ks++) {
                const int kc = ks * 16 + khalf;
                uint32_t a[2][4];
                #pragma unroll
                for (int i = 0; i < 2; i++)
                    ldm_x4(a[i][0], a[i][1], a[i][2], a[i][3],
                           ab + (uint32_t)((wm + i * 16 + lrow16) * LDT + kc) * 2u);
                #pragma unroll
                for (int jj = 0; jj < 4; jj++) {
                    uint32_t b0, b1, b2, b3;
                    ldm_x4(b0, b1, b2, b3,
                           bb + (uint32_t)((wn + jj * 16 + lrow16) * LDT + kc) * 2u);
                    #pragma unroll
                    for (int i = 0; i < 2; i++) {
                        mma16816(acc[i][2 * jj + 0], a[i][0], a[i][1], a[i][2], a[i][3], b0, b2);
                        mma16816(acc[i][2 * jj + 1], a[i][0], a[i][1], a[i][2], a[i][3], b1, b3);
                    }
                }
            }
            __syncthreads();              // all warps done with stage q&1
            if (q + 2 < QMAX) loadA(q + 2);  // safe to overwrite now
        }

        // ---- Poincare epilogue for this m-tile (overlaps in-flight A loads)
        float xs[2][2], one_m_xs[2][2];
        #pragma unroll
        for (int i = 0; i < 2; i++)
            #pragma unroll
            for (int h = 0; h < 2; h++) {
                const int m = m0 + wm + i * 16 + g + h * 8;
                xs[i][h] = xsq[m];
                one_m_xs[i][h] = 1.f - xs[i][h];
            }

        #pragma unroll
        for (int j = 0; j < 8; j++) {
            const int nb = n0 + wn + j * 8 + tg * 2;
            if (nb >= NCLS) continue;
            const float ps0 = psq[nb], ps1 = psq[nb + 1];
            const float omp0 = 1.f - ps0, omp1 = 1.f - ps1;
            #pragma unroll
            for (int i = 0; i < 2; i++) {
                #pragma unroll
                for (int h = 0; h < 2; h++) {
                    const int m = m0 + wm + i * 16 + g + h * 8;
                    const float xsv = xs[i][h];
                    const float omx = one_m_xs[i][h];

                    float d0 = fmaxf(xsv + ps0 - 2.f * acc[i][j][2 * h + 0], 0.f);
                    float d1 = fmaxf(xsv + ps1 - 2.f * acc[i][j][2 * h + 1], 0.f);
                    float de0 = fmaxf(omx * omp0, EPS_F);
                    float de1 = fmaxf(omx * omp1, EPS_F);
                    float a0 = fmaxf(1.f + 2.f * d0 / de0, 1.f + EPS_F);
                    float a1 = fmaxf(1.f + 2.f * d1 / de1, 1.f + EPS_F);
                    float r0 = __logf(a0 + __fsqrt_rn(a0 * a0 - 1.f));
                    float r1 = __logf(a1 + __fsqrt_rn(a1 * a1 - 1.f));
                    float2 v = make_float2(-r0 * lscale, -r1 * lscale);
                    *(float2*)&Out[(size_t)m * NCLS + nb] = v;
                }
            }
        }
    }
}

// ---------------------------------------------------------------------------
// Launch
// ---------------------------------------------------------------------------
extern "C" void kernel_launch(void* const* d_in, const int* in_sizes, int n_in,
                              void* d_out, int out_size)
{
    const float* features    = (const float*)d_in[0];
    const float* W           = (const float*)d_in[1];
    const float* bias        = (const float*)d_in[2];
    const float* embeddings  = (const float*)d_in[3];
    const float* logit_scale = (const float*)d_in[4];
    float* out = (float*)d_out;

    __nv_bfloat16 *featb, *Wb, *xb, *pb;
    float *xsq, *psq;
    cudaGetSymbolAddress((void**)&featb, g_featb);
    cudaGetSymbolAddress((void**)&Wb,    g_Wb);
    cudaGetSymbolAddress((void**)&xb,    g_xb);
    cudaGetSymbolAddress((void**)&xsq,   g_xsq);
    cudaGetSymbolAddress((void**)&pb,    g_pb);
    cudaGetSymbolAddress((void**)&psq,   g_psq);

    // 1. Convert inputs to bf16
    f2b_kernel<<<(MROWS * DIM / 4 + 255) / 256, 256>>>(features, featb, MROWS * DIM);
    f2b_kernel<<<(DIM * DIM / 4 + 255) / 256, 256>>>(W, Wb, DIM * DIM);

    // 2. Fused proj GEMM + expmap (3-stage cp.async)
    cudaFuncSetAttribute(proj_expmap_kernel,
                         cudaFuncAttributeMaxDynamicSharedMemorySize, PROJ_SMEM);
    proj_expmap_kernel<<<MROWS / PM, 256, PROJ_SMEM>>>(featb, Wb, bias, xb, xsq);

    // 3. expmap0 on embeddings
    expmap_kernel<<<NCLS, DIM>>>(embeddings, pb, psq);

    // 4. Logits GEMM (persistent-B) + Poincare epilogue
    cudaFuncSetAttribute(logits_mma_kernel,
                         cudaFuncAttributeMaxDynamicSharedMemorySize, LG_SMEM);
    {
        dim3 grid((NCLS + BN - 1) / BN, MROWS / (BM * MT));  // (8, 32)
        logits_mma_kernel<<<grid, 256, LG_SMEM>>>(xb, pb, xsq, psq,
                                                  logit_scale, out);
    }
}

// round 10
// speedup vs baseline: 1.4435x; 1.4435x over previous
#include <cuda_runtime.h>
#include <cuda_bf16.h>
#include <math.h>
#include <stdint.h>

// Problem constants
#define BATCH   4
#define SEQ     8192
#define MROWS   (BATCH * SEQ)   // 32768
#define DIM     256
#define NCLS    1000
#define EPS_F   1e-5f

#define BK  32
#define LDT 40                  // 80B padded row: 16B-aligned, ldmatrix-clean

// Proj: CTA 128x256, 16 warps (4M x 4N), warp 32x64. W resident in smem.
#define PM 128
// smem: W 8 chunks x 256 x LDT halves, A 2 stages x 128 x LDT halves
#define W_CHUNK_H (256 * LDT)                  // halves per k-chunk of W
#define A_STG_H   (PM * LDT)
#define PROJ_SMEM ((8 * W_CHUNK_H + 2 * A_STG_H) * 2)   // 184320 B

// Logits: 128x128 CTA, 8 warps (4M x 2N), warp 32x64, 3-stage cp.async
#define BM 128
#define BN 128
#define STG 3
#define STG_BYTES (BM * LDT * 2)               // 10240 B
#define LOGITS_SMEM (STG * 2 * STG_BYTES)      // 61440 B

// Scratch
__device__ __nv_bfloat16 g_xb[MROWS * DIM];
__device__ float         g_xsq[MROWS];
__device__ __nv_bfloat16 g_pb[NCLS * DIM];
__device__ float         g_psq[NCLS];

// ---------------------------------------------------------------------------
// PTX helpers (base-sm_103-legal only)
// ---------------------------------------------------------------------------
__device__ __forceinline__ uint32_t smem_u32(const void* p) {
    return (uint32_t)__cvta_generic_to_shared(p);
}
__device__ __forceinline__ void cp16s(uint32_t dst_saddr, const void* src, bool valid)
{
    int sz = valid ? 16 : 0;
    asm volatile("cp.async.cg.shared.global [%0], [%1], 16, %2;\n"
                 :: "r"(dst_saddr), "l"(src), "r"(sz));
}
#define CP_COMMIT() asm volatile("cp.async.commit_group;\n" ::: "memory")
#define CP_WAIT(n)  asm volatile("cp.async.wait_group %0;\n" :: "n"(n) : "memory")

__device__ __forceinline__ void ldm_x4(uint32_t& r0, uint32_t& r1,
                                       uint32_t& r2, uint32_t& r3, uint32_t saddr)
{
    asm volatile("ldmatrix.sync.aligned.m8n8.x4.shared.b16 {%0,%1,%2,%3}, [%4];"
                 : "=r"(r0), "=r"(r1), "=r"(r2), "=r"(r3) : "r"(saddr));
}

__device__ __forceinline__ void mma16816(float acc[4], uint32_t a0, uint32_t a1,
                                         uint32_t a2, uint32_t a3,
                                         uint32_t b0, uint32_t b1)
{
    asm volatile(
        "mma.sync.aligned.m16n8k16.row.col.f32.bf16.bf16.f32 "
        "{%0,%1,%2,%3}, {%4,%5,%6,%7}, {%8,%9}, {%0,%1,%2,%3};\n"
        : "+f"(acc[0]), "+f"(acc[1]), "+f"(acc[2]), "+f"(acc[3])
        : "r"(a0), "r"(a1), "r"(a2), "r"(a3), "r"(b0), "r"(b1));
}

__device__ __forceinline__ float fsqrt_approx(float x) {
    float y;
    asm("sqrt.approx.f32 %0, %1;" : "=f"(y) : "f"(x));
    return y;
}

// ---------------------------------------------------------------------------
// Proj: xb = expmap0(features @ W^T + b). W resident in smem (bf16),
// A fp32-LDG prefetched one kt ahead, double-buffered bf16 staging.
// ---------------------------------------------------------------------------
__global__ __launch_bounds__(512, 1)
void proj_expmap_kernel(const float* __restrict__ A,
                        const float* __restrict__ W,
                        const float* __restrict__ bias,
                        __nv_bfloat16* __restrict__ Xb,
                        float* __restrict__ xsq_out)
{
    extern __shared__ __nv_bfloat16 dsm[];
    const uint32_t wbase = smem_u32(dsm);                       // W: 8 chunks
    const uint32_t abase = wbase + 8u * W_CHUNK_H * 2u;         // A: 2 stages
    __shared__ float rowsum[PM];
    __shared__ float rowscale[PM];

    const int tid = threadIdx.x;          // 512
    const int m0  = blockIdx.x * PM;
    if (tid < PM) rowsum[tid] = 0.f;

    const int warp = tid >> 5;            // 0..15
    const int lane = tid & 31;
    const int wm = (warp & 3) * 32;
    const int wn = (warp >> 2) * 64;
    const int g  = lane >> 2;
    const int tg = lane & 3;
    const int lrow16 = lane & 15;
    const int khalf  = (lane >> 4) << 3;

    // ---- load + convert ALL of W into smem (once per CTA)
    // 16384 float4 slots; 32 per thread. idx*4 linear: r=idx>>6, c=(idx&63)*4
    #pragma unroll
    for (int it = 0; it < 32; it++) {
        int idx = tid + it * 512;
        int r = idx >> 6;
        int c4 = (idx & 63) * 4;
        float4 v = *(const float4*)&W[(size_t)r * DIM + c4];
        __nv_bfloat162 lo = __floats2bfloat162_rn(v.x, v.y);
        __nv_bfloat162 hi = __floats2bfloat162_rn(v.z, v.w);
        uint2 pk; pk.x = *(uint32_t*)&lo; pk.y = *(uint32_t*)&hi;
        int chunk = c4 >> 5;
        int cc = c4 & 31;
        *(uint2*)(dsm + (size_t)(chunk * 256 + r) * LDT + cc) = pk;
    }

    // ---- prefetch A for kt=0 into registers
    // 128 rows x 32 fp32 = 1024 float4; 2 per thread
    const int arow0 = tid >> 2;                   // rows 0..127 (x2 halves? no):
    // idx = tid + r*512 : row = idx>>3? We need 1024 slots over 512 thr x2.
    float4 apf[2];
    {
        #pragma unroll
        for (int r = 0; r < 2; r++) {
            int idx = tid + r * 512;
            int row = idx >> 3;
            int cc = (idx & 7) * 4;
            apf[r] = *(const float4*)&A[(size_t)(m0 + row) * DIM + 0 + cc];
        }
    }
    __syncthreads();   // W smem ready (also covers rowsum init)

    float acc[2][8][4];
    #pragma unroll
    for (int i = 0; i < 2; i++)
        #pragma unroll
        for (int j = 0; j < 8; j++)
            #pragma unroll
            for (int e = 0; e < 4; e++) acc[i][j][e] = 0.f;

    for (int kt = 0; kt < 8; kt++) {
        // store prefetched A (convert to bf16) into stage kt&1
        const uint32_t ast = abase + (uint32_t)((kt & 1) * A_STG_H) * 2u;
        #pragma unroll
        for (int r = 0; r < 2; r++) {
            int idx = tid + r * 512;
            int row = idx >> 3;
            int cc = (idx & 7) * 4;
            __nv_bfloat162 lo = __floats2bfloat162_rn(apf[r].x, apf[r].y);
            __nv_bfloat162 hi = __floats2bfloat162_rn(apf[r].z, apf[r].w);
            uint2 pk; pk.x = *(uint32_t*)&lo; pk.y = *(uint32_t*)&hi;
            *(uint2*)(dsm + (size_t)(8 * W_CHUNK_H) + (size_t)((kt & 1) * PM + row) * LDT + cc) = pk;
        }
        __syncthreads();

        // prefetch next kt's A (latency hidden behind MMA)
        if (kt < 7) {
            const int k0 = (kt + 1) * BK;
            #pragma unroll
            for (int r = 0; r < 2; r++) {
                int idx = tid + r * 512;
                int row = idx >> 3;
                int cc = (idx & 7) * 4;
                apf[r] = *(const float4*)&A[(size_t)(m0 + row) * DIM + k0 + cc];
            }
        }

        const uint32_t bb = wbase + (uint32_t)(kt * W_CHUNK_H) * 2u;
        #pragma unroll
        for (int ks = 0; ks < 2; ks++) {
            const int kc = ks * 16 + khalf;
            uint32_t a[2][4];
            #pragma unroll
            for (int i = 0; i < 2; i++)
                ldm_x4(a[i][0], a[i][1], a[i][2], a[i][3],
                       ast + (uint32_t)((wm + i * 16 + lrow16) * LDT + kc) * 2u);
            #pragma unroll
            for (int jj = 0; jj < 4; jj++) {
                uint32_t b0, b1, b2, b3;
                ldm_x4(b0, b1, b2, b3,
                       bb + (uint32_t)((wn + jj * 16 + lrow16) * LDT + kc) * 2u);
                #pragma unroll
                for (int i = 0; i < 2; i++) {
                    mma16816(acc[i][2 * jj + 0], a[i][0], a[i][1], a[i][2], a[i][3], b0, b2);
                    mma16816(acc[i][2 * jj + 1], a[i][0], a[i][1], a[i][2], a[i][3], b1, b3);
                }
            }
        }
        __syncthreads();   // stage consumed; safe to overwrite next iteration
    }

    // ---- epilogue: bias, row sumsq, expmap, write bf16 + xsq
    float part[2][2] = {{0.f, 0.f}, {0.f, 0.f}};
    #pragma unroll
    for (int j = 0; j < 8; j++) {
        const int nb = wn + j * 8 + tg * 2;
        const float b0 = bias[nb], b1 = bias[nb + 1];
        #pragma unroll
        for (int i = 0; i < 2; i++) {
            #pragma unroll
            for (int h = 0; h < 2; h++) {
                float y0 = acc[i][j][2 * h + 0] + b0;
                float y1 = acc[i][j][2 * h + 1] + b1;
                acc[i][j][2 * h + 0] = y0;
                acc[i][j][2 * h + 1] = y1;
                part[i][h] += y0 * y0 + y1 * y1;
            }
        }
    }
    #pragma unroll
    for (int i = 0; i < 2; i++)
        #pragma unroll
        for (int h = 0; h < 2; h++)
            atomicAdd(&rowsum[wm + i * 16 + g + h * 8], part[i][h]);
    __syncthreads();

    if (tid < PM) {
        const float total = rowsum[tid];
        const float norm  = sqrtf(total);
        const float cn    = fmaxf(norm, EPS_F);
        const float s     = tanhf(cn) / cn;
        rowscale[tid] = s;
        xsq_out[m0 + tid] = s * s * total;
    }
    __syncthreads();

    #pragma unroll
    for (int i = 0; i < 2; i++) {
        #pragma unroll
        for (int h = 0; h < 2; h++) {
            const int ml = wm + i * 16 + g + h * 8;
            const float s = rowscale[ml];
            const int m = m0 + ml;
            #pragma unroll
            for (int j = 0; j < 8; j++) {
                const int nb = wn + j * 8 + tg * 2;
                __nv_bfloat162 v = __floats2bfloat162_rn(
                    s * acc[i][j][2 * h + 0], s * acc[i][j][2 * h + 1]);
                *(__nv_bfloat162*)&Xb[(size_t)m * DIM + nb] = v;
            }
        }
    }
}

// ---------------------------------------------------------------------------
// expmap0 for embeddings
// ---------------------------------------------------------------------------
__global__ void expmap_kernel(const float* __restrict__ src,
                              __nv_bfloat16* __restrict__ dst,
                              float* __restrict__ sq_out)
{
    const int row = blockIdx.x;
    const int tid = threadIdx.x;
    const float v = src[(size_t)row * DIM + tid];

    float s = v * v;
    #pragma unroll
    for (int off = 16; off > 0; off >>= 1)
        s += __shfl_xor_sync(0xFFFFFFFFu, s, off);

    __shared__ float warp_s[8];
    __shared__ float total_sh;
    const int warp = tid >> 5;
    if ((tid & 31) == 0) warp_s[warp] = s;
    __syncthreads();
    if (tid == 0) {
        float t = 0.f;
        #pragma unroll
        for (int w = 0; w < 8; w++) t += warp_s[w];
        total_sh = t;
    }
    __syncthreads();

    const float total = total_sh;
    const float norm  = sqrtf(total);
    const float cn    = fmaxf(norm, EPS_F);
    const float scale = tanhf(cn) / cn;

    dst[(size_t)row * DIM + tid] = __float2bfloat16(scale * v);
    if (tid == 0) sq_out[row] = scale * scale * total;
}

// ---------------------------------------------------------------------------
// Logits GEMM: 3-stage cp.async + ldmatrix + HMMA + approx Poincare epilogue
// ---------------------------------------------------------------------------
__global__ __launch_bounds__(256, 2)
void logits_mma_kernel(const __nv_bfloat16* __restrict__ Xb,
                       const __nv_bfloat16* __restrict__ Pb,
                       const float* __restrict__ xsq,
                       const float* __restrict__ psq,
                       const float* __restrict__ logit_scale,
                       float* __restrict__ Out)
{
    extern __shared__ __nv_bfloat16 dsm[];
    const uint32_t base = smem_u32(dsm);
    const uint32_t aoff[STG] = {0u, STG_BYTES, 2u * STG_BYTES};
    const uint32_t boff0 = STG * STG_BYTES;

    const int tid  = threadIdx.x;
    const int m0 = blockIdx.y * BM;
    const int n0 = blockIdx.x * BN;

    const int warp = tid >> 5;
    const int lane = tid & 31;
    const int wm = (warp & 3) * 32;
    const int wn = (warp >> 2) * 64;
    const int g  = lane >> 2;
    const int tg = lane & 3;
    const int lrow16 = lane & 15;
    const int khalf  = (lane >> 4) << 3;

    const int lrow = tid >> 2;
    const int lch  = (tid & 3) * 8;

    float acc[2][8][4];
    #pragma unroll
    for (int i = 0; i < 2; i++)
        #pragma unroll
        for (int j = 0; j < 8; j++)
            #pragma unroll
            for (int e = 0; e < 4; e++) acc[i][j][e] = 0.f;

    const int NKT = DIM / BK;   // 8

    auto load_stage = [&](int kt, int st) {
        const int k0 = kt * BK;
        #pragma unroll
        for (int r = 0; r < 2; r++) {
            int row = lrow + r * 64;
            uint32_t d = (uint32_t)(row * LDT + lch) * 2u;
            cp16s(base + aoff[st] + d,
                  &Xb[(size_t)(m0 + row) * DIM + k0 + lch], true);
            cp16s(base + boff0 + aoff[st] + d,
                  &Pb[(size_t)(n0 + row) * DIM + k0 + lch], (n0 + row) < NCLS);
        }
        CP_COMMIT();
    };

    load_stage(0, 0);
    load_stage(1, 1);

    for (int kt = 0; kt < NKT; kt++) {
        if (kt + 2 < NKT)
            asm volatile("cp.async.wait_group 1;\n" ::: "memory");
        else
            asm volatile("cp.async.wait_group 0;\n" ::: "memory");
        __syncthreads();

        if (kt + 2 < NKT) load_stage(kt + 2, (kt + 2) % STG);

        const int st = kt % STG;
        const uint32_t ab = base + aoff[st];
        const uint32_t bb = base + boff0 + aoff[st];

        #pragma unroll
        for (int ks = 0; ks < 2; ks++) {
            const int kc = ks * 16 + khalf;
            uint32_t a[2][4];
            #pragma unroll
            for (int i = 0; i < 2; i++)
                ldm_x4(a[i][0], a[i][1], a[i][2], a[i][3],
                       ab + (uint32_t)((wm + i * 16 + lrow16) * LDT + kc) * 2u);
            #pragma unroll
            for (int jj = 0; jj < 4; jj++) {
                uint32_t b0, b1, b2, b3;
                ldm_x4(b0, b1, b2, b3,
                       bb + (uint32_t)((wn + jj * 16 + lrow16) * LDT + kc) * 2u);
                #pragma unroll
                for (int i = 0; i < 2; i++) {
                    mma16816(acc[i][2 * jj + 0], a[i][0], a[i][1], a[i][2], a[i][3], b0, b2);
                    mma16816(acc[i][2 * jj + 1], a[i][0], a[i][1], a[i][2], a[i][3], b1, b3);
                }
            }
        }
        // single sync per iteration: next overwrite of this stage happens
        // after the NEXT top-of-loop barrier, which orders all reads.
    }

    // ---- Poincare epilogue (approx MUFU math)
    const float lscale = fminf(expf(logit_scale[0]), 100.f);

    float xs[2][2], one_m_xs[2][2];
    #pragma unroll
    for (int i = 0; i < 2; i++)
        #pragma unroll
        for (int h = 0; h < 2; h++) {
            const int m = m0 + wm + i * 16 + g + h * 8;
            xs[i][h] = xsq[m];
            one_m_xs[i][h] = 1.f - xs[i][h];
        }

    #pragma unroll
    for (int j = 0; j < 8; j++) {
        const int nb = n0 + wn + j * 8 + tg * 2;
        if (nb >= NCLS) continue;              // NCLS even -> pairs in/out together
        const float ps0 = psq[nb], ps1 = psq[nb + 1];
        const float omp0 = 1.f - ps0, omp1 = 1.f - ps1;
        #pragma unroll
        for (int i = 0; i < 2; i++) {
            #pragma unroll
            for (int h = 0; h < 2; h++) {
                const int m = m0 + wm + i * 16 + g + h * 8;
                const float xsv = xs[i][h];
                const float omx = one_m_xs[i][h];

                float d0 = fmaxf(xsv + ps0 - 2.f * acc[i][j][2 * h + 0], 0.f);
                float d1 = fmaxf(xsv + ps1 - 2.f * acc[i][j][2 * h + 1], 0.f);
                float de0 = fmaxf(omx * omp0, EPS_F);
                float de1 = fmaxf(omx * omp1, EPS_F);
                float a0 = fmaxf(fmaf(2.f, __fdividef(d0, de0), 1.f), 1.f + EPS_F);
                float a1 = fmaxf(fmaf(2.f, __fdividef(d1, de1), 1.f), 1.f + EPS_F);
                float r0 = __logf(a0 + fsqrt_approx(fmaf(a0, a0, -1.f)));
                float r1 = __logf(a1 + fsqrt_approx(fmaf(a1, a1, -1.f)));
                float2 v = make_float2(-r0 * lscale, -r1 * lscale);
                *(float2*)&Out[(size_t)m * NCLS + nb] = v;
            }
        }
    }
}

// ---------------------------------------------------------------------------
// Launch
// ---------------------------------------------------------------------------
extern "C" void kernel_launch(void* const* d_in, const int* in_sizes, int n_in,
                              void* d_out, int out_size)
{
    const float* features    = (const float*)d_in[0];
    const float* W           = (const float*)d_in[1];
    const float* bias        = (const float*)d_in[2];
    const float* embeddings  = (const float*)d_in[3];
    const float* logit_scale = (const float*)d_in[4];
    float* out = (float*)d_out;

    __nv_bfloat16 *xb, *pb;
    float *xsq, *psq;
    cudaGetSymbolAddress((void**)&xb,  g_xb);
    cudaGetSymbolAddress((void**)&xsq, g_xsq);
    cudaGetSymbolAddress((void**)&pb,  g_pb);
    cudaGetSymbolAddress((void**)&psq, g_psq);

    // 1. Fused proj (W-resident smem, A prefetch) + expmap -> xb, xsq
    cudaFuncSetAttribute(proj_expmap_kernel,
                         cudaFuncAttributeMaxDynamicSharedMemorySize, PROJ_SMEM);
    proj_expmap_kernel<<<MROWS / PM, 512, PROJ_SMEM>>>(features, W, bias, xb, xsq);

    // 2. expmap0 on embeddings
    expmap_kernel<<<NCLS, DIM>>>(embeddings, pb, psq);

    // 3. Logits GEMM (3-stage pipeline, single-sync mainloop) + approx epilogue
    cudaFuncSetAttribute(logits_mma_kernel,
                         cudaFuncAttributeMaxDynamicSharedMemorySize, LOGITS_SMEM);
    {
        dim3 grid((NCLS + BN - 1) / BN, MROWS / BM);   // (8, 256)
        logits_mma_kernel<<<grid, 256, LOGITS_SMEM>>>(xb, pb, xsq, psq,
                                                      logit_scale, out);
    }
}